// round 1
// baseline (speedup 1.0000x reference)
#include <cuda_runtime.h>
#include <cuda_bf16.h>

#define D_IN  128
#define D_OUT 64
#define TM    64
#define EPT   128   // edges per chunk

// scratch for h = x @ W  (50000 x 64 fp32 = 12.8 MB)
__device__ float g_h[50000 * D_OUT];

// ---------------------------------------------------------------------------
// out[i, c] = bias[c]
// ---------------------------------------------------------------------------
__global__ void init_out_kernel(float* __restrict__ out,
                                const float* __restrict__ bias,
                                int total) {
    int i = blockIdx.x * blockDim.x + threadIdx.x;
    if (i < total) out[i] = __ldg(bias + (i & (D_OUT - 1)));
}

// ---------------------------------------------------------------------------
// h = x @ W.  TM=64 rows per block, 128 threads.
// Xs transposed [k][row] (32 KB smem), W via __ldg (L1-resident 32 KB).
// Each thread: 8 rows x 4 cols of output.
// ---------------------------------------------------------------------------
__global__ void __launch_bounds__(128)
gemm_kernel(const float* __restrict__ x,
            const float* __restrict__ w,
            int n_nodes) {
    __shared__ float Xs[D_IN][TM];   // 32 KB

    int tid  = threadIdx.x;
    int row0 = blockIdx.x * TM;

    // load x tile transposed: TM rows x 128 cols as float4
    for (int i = tid; i < TM * (D_IN / 4); i += 128) {
        int r  = i >> 5;            // row within tile (D_IN/4 = 32 quads/row)
        int kq = (i & 31) << 2;     // k base
        int gr = row0 + r;
        float4 v = make_float4(0.f, 0.f, 0.f, 0.f);
        if (gr < n_nodes)
            v = *(const float4*)(x + (size_t)gr * D_IN + kq);
        Xs[kq + 0][r] = v.x;
        Xs[kq + 1][r] = v.y;
        Xs[kq + 2][r] = v.z;
        Xs[kq + 3][r] = v.w;
    }
    __syncthreads();

    int cg = (tid & 15) << 2;   // column base (16 col-groups of 4)
    int rg = (tid >> 4) << 3;   // row base    (8 row-groups of 8)

    float acc[8][4];
    #pragma unroll
    for (int j = 0; j < 8; j++)
        #pragma unroll
        for (int c = 0; c < 4; c++) acc[j][c] = 0.f;

    #pragma unroll 4
    for (int k = 0; k < D_IN; k++) {
        float4 wv = __ldg((const float4*)(w + k * D_OUT + cg));
        float4 xa = *(const float4*)(&Xs[k][rg]);
        float4 xb = *(const float4*)(&Xs[k][rg + 4]);
        float xr[8] = {xa.x, xa.y, xa.z, xa.w, xb.x, xb.y, xb.z, xb.w};
        #pragma unroll
        for (int j = 0; j < 8; j++) {
            acc[j][0] += xr[j] * wv.x;
            acc[j][1] += xr[j] * wv.y;
            acc[j][2] += xr[j] * wv.z;
            acc[j][3] += xr[j] * wv.w;
        }
    }

    #pragma unroll
    for (int j = 0; j < 8; j++) {
        int gr = row0 + rg + j;
        if (gr < n_nodes)
            *(float4*)(g_h + (size_t)gr * D_OUT + cg) =
                make_float4(acc[j][0], acc[j][1], acc[j][2], acc[j][3]);
    }
}

// ---------------------------------------------------------------------------
// Segment-accumulated scatter.  edge_dst is sorted, avg degree 16:
// thread (c, y) walks EPT edges of chunk (blockIdx*4 + y), keeping a running
// accumulator for column c and flushing one atomicAdd per dst change.
// blockDim = (64, 4).  h gather per warp = 128 B coalesced, L2-resident.
// ---------------------------------------------------------------------------
__global__ void __launch_bounds__(256)
scatter_kernel(const int*   __restrict__ src,
               const int*   __restrict__ dst,
               const float* __restrict__ vals,
               float*       __restrict__ out,
               int n_edges) {
    int c = threadIdx.x;                       // 0..63 column
    long long chunk = (long long)blockIdx.x * 4 + threadIdx.y;
    long long e0 = chunk * EPT;
    if (e0 >= n_edges) return;
    long long e1 = e0 + EPT;
    if (e1 > n_edges) e1 = n_edges;

    int   prev = __ldg(dst + e0);
    float acc  = 0.f;

    for (long long e = e0; e < e1; e++) {
        int   s = __ldg(src + e);
        int   d = __ldg(dst + e);
        float v = __ldg(vals + e);
        float hv = g_h[(size_t)s * D_OUT + c];
        if (d != prev) {
            atomicAdd(out + (size_t)prev * D_OUT + c, acc);
            acc  = 0.f;
            prev = d;
        }
        acc += v * hv;
    }
    atomicAdd(out + (size_t)prev * D_OUT + c, acc);
}

// ---------------------------------------------------------------------------
extern "C" void kernel_launch(void* const* d_in, const int* in_sizes, int n_in,
                              void* d_out, int out_size) {
    const float* x     = (const float*)d_in[0];
    const int*   esrc  = (const int*)  d_in[1];
    const int*   edst  = (const int*)  d_in[2];
    const float* evals = (const float*)d_in[3];
    const float* w     = (const float*)d_in[4];
    const float* bias  = (const float*)d_in[5];
    float*       out   = (float*)d_out;

    int n_nodes = in_sizes[0] / D_IN;
    int n_edges = in_sizes[1];

    int total = n_nodes * D_OUT;
    init_out_kernel<<<(total + 255) / 256, 256>>>(out, bias, total);

    gemm_kernel<<<(n_nodes + TM - 1) / TM, 128>>>(x, w, n_nodes);

    int nchunks = (n_edges + EPT - 1) / EPT;
    dim3 bd(64, 4);
    scatter_kernel<<<(nchunks + 3) / 4, bd>>>(esrc, edst, evals, out, n_edges);
}

// round 2
// speedup vs baseline: 1.3799x; 1.3799x over previous
#include <cuda_runtime.h>
#include <cuda_bf16.h>

#define D_IN  128
#define D_OUT 64
#define TM    64
#define MAX_NODES 50000

// scratch: h = x @ W  (50000 x 64 fp32 = 12.8 MB), CSR row pointers
__device__ float g_h[MAX_NODES * D_OUT];
__device__ int   g_row_ptr[MAX_NODES + 1];

// ---------------------------------------------------------------------------
// CSR row offsets from sorted edge_dst: row_ptr[i] = first e with dst[e] >= i
// ---------------------------------------------------------------------------
__global__ void rowptr_kernel(const int* __restrict__ dst,
                              int n_edges, int n_nodes) {
    int i = blockIdx.x * blockDim.x + threadIdx.x;
    if (i > n_nodes) return;
    int lo = 0, hi = n_edges;
    while (lo < hi) {
        int mid = (lo + hi) >> 1;
        if (__ldg(dst + mid) < i) lo = mid + 1;
        else                      hi = mid;
    }
    g_row_ptr[i] = lo;
}

// ---------------------------------------------------------------------------
// h = x @ W.  TM=64 rows per block, 128 threads.
// Xs transposed [k][row] (32 KB smem), W via __ldg (L1-resident 32 KB).
// Each thread: 8 rows x 4 cols of output.
// ---------------------------------------------------------------------------
__global__ void __launch_bounds__(128)
gemm_kernel(const float* __restrict__ x,
            const float* __restrict__ w,
            int n_nodes) {
    __shared__ float Xs[D_IN][TM];   // 32 KB

    int tid  = threadIdx.x;
    int row0 = blockIdx.x * TM;

    for (int i = tid; i < TM * (D_IN / 4); i += 128) {
        int r  = i >> 5;
        int kq = (i & 31) << 2;
        int gr = row0 + r;
        float4 v = make_float4(0.f, 0.f, 0.f, 0.f);
        if (gr < n_nodes)
            v = *(const float4*)(x + (size_t)gr * D_IN + kq);
        Xs[kq + 0][r] = v.x;
        Xs[kq + 1][r] = v.y;
        Xs[kq + 2][r] = v.z;
        Xs[kq + 3][r] = v.w;
    }
    __syncthreads();

    int cg = (tid & 15) << 2;   // column base
    int rg = (tid >> 4) << 3;   // row base

    float acc[8][4];
    #pragma unroll
    for (int j = 0; j < 8; j++)
        #pragma unroll
        for (int c = 0; c < 4; c++) acc[j][c] = 0.f;

    #pragma unroll 4
    for (int k = 0; k < D_IN; k++) {
        float4 wv = __ldg((const float4*)(w + k * D_OUT + cg));
        float4 xa = *(const float4*)(&Xs[k][rg]);
        float4 xb = *(const float4*)(&Xs[k][rg + 4]);
        float xr[8] = {xa.x, xa.y, xa.z, xa.w, xb.x, xb.y, xb.z, xb.w};
        #pragma unroll
        for (int j = 0; j < 8; j++) {
            acc[j][0] += xr[j] * wv.x;
            acc[j][1] += xr[j] * wv.y;
            acc[j][2] += xr[j] * wv.z;
            acc[j][3] += xr[j] * wv.w;
        }
    }

    #pragma unroll
    for (int j = 0; j < 8; j++) {
        int gr = row0 + rg + j;
        if (gr < n_nodes)
            *(float4*)(g_h + (size_t)gr * D_OUT + cg) =
                make_float4(acc[j][0], acc[j][1], acc[j][2], acc[j][3]);
    }
}

// ---------------------------------------------------------------------------
// Warp-per-node aggregation.  Lane c owns columns [2c, 2c+1] (float2).
// Per edge: uniform src/val broadcast + one 256B coalesced h-row gather.
// No atomics; bias fused into the final store.
// ---------------------------------------------------------------------------
__global__ void __launch_bounds__(256)
gather_kernel(const int*   __restrict__ src,
              const float* __restrict__ vals,
              const float* __restrict__ bias,
              float*       __restrict__ out,
              int n_nodes) {
    int gwarp = (blockIdx.x * 256 + threadIdx.x) >> 5;
    int lane  = threadIdx.x & 31;
    if (gwarp >= n_nodes) return;

    int e0 = g_row_ptr[gwarp];
    int e1 = g_row_ptr[gwarp + 1];

    const float2* hp = (const float2*)g_h;
    float ax = 0.f, ay = 0.f;

    int e = e0;
    // 2-wide software pipeline for MLP on the src->h chain
    for (; e + 1 < e1; e += 2) {
        int   s0 = __ldg(src + e);
        int   s1 = __ldg(src + e + 1);
        float v0 = __ldg(vals + e);
        float v1 = __ldg(vals + e + 1);
        float2 h0 = hp[(size_t)s0 * 32 + lane];
        float2 h1 = hp[(size_t)s1 * 32 + lane];
        ax += v0 * h0.x + v1 * h1.x;
        ay += v0 * h0.y + v1 * h1.y;
    }
    if (e < e1) {
        int   s0 = __ldg(src + e);
        float v0 = __ldg(vals + e);
        float2 h0 = hp[(size_t)s0 * 32 + lane];
        ax += v0 * h0.x;
        ay += v0 * h0.y;
    }

    float2 b = __ldg((const float2*)bias + lane);
    ((float2*)out)[(size_t)gwarp * 32 + lane] = make_float2(ax + b.x, ay + b.y);
}

// ---------------------------------------------------------------------------
extern "C" void kernel_launch(void* const* d_in, const int* in_sizes, int n_in,
                              void* d_out, int out_size) {
    const float* x     = (const float*)d_in[0];
    const int*   esrc  = (const int*)  d_in[1];
    const int*   edst  = (const int*)  d_in[2];
    const float* evals = (const float*)d_in[3];
    const float* w     = (const float*)d_in[4];
    const float* bias  = (const float*)d_in[5];
    float*       out   = (float*)d_out;

    int n_nodes = in_sizes[0] / D_IN;
    int n_edges = in_sizes[1];

    rowptr_kernel<<<(n_nodes + 256) / 256, 256>>>(edst, n_edges, n_nodes);

    gemm_kernel<<<(n_nodes + TM - 1) / TM, 128>>>(x, w, n_nodes);

    int warps_needed = n_nodes;
    gather_kernel<<<(warps_needed * 32 + 255) / 256, 256>>>(esrc, evals, bias, out, n_nodes);
}

// round 3
// speedup vs baseline: 1.4125x; 1.0236x over previous
#include <cuda_runtime.h>
#include <cuda_bf16.h>

#define D_IN  128
#define D_OUT 64
#define TM    64
#define MAX_NODES 50000

// scratch: h = x @ W  (50000 x 64 fp32 = 12.8 MB), CSR row pointers
__device__ float g_h[MAX_NODES * D_OUT];
__device__ int   g_row_ptr[MAX_NODES + 1];

// ---------------------------------------------------------------------------
// CSR row offsets via boundary detection on sorted edge_dst.
// row_ptr[i] = first e with dst[e] >= i.  Thread e owns nodes (dst[e-1], dst[e]].
// ---------------------------------------------------------------------------
__global__ void rowptr_kernel(const int* __restrict__ dst,
                              int n_edges, int n_nodes) {
    int e = blockIdx.x * blockDim.x + threadIdx.x;
    if (e >= n_edges) return;
    int b = __ldg(dst + e);
    int a = (e == 0) ? -1 : __ldg(dst + e - 1);
    for (int i = a + 1; i <= b; i++) g_row_ptr[i] = e;
    if (e == n_edges - 1)
        for (int i = b + 1; i <= n_nodes; i++) g_row_ptr[i] = n_edges;
}

// ---------------------------------------------------------------------------
// h = x @ W.  TM=64 rows per block, 128 threads.
// Xs transposed [k][row] (32 KB smem), W via __ldg (L1-resident 32 KB).
// Each thread: 8 rows x 4 cols of output.
// ---------------------------------------------------------------------------
__global__ void __launch_bounds__(128)
gemm_kernel(const float* __restrict__ x,
            const float* __restrict__ w,
            int n_nodes) {
    __shared__ float Xs[D_IN][TM];   // 32 KB

    int tid  = threadIdx.x;
    int row0 = blockIdx.x * TM;

    for (int i = tid; i < TM * (D_IN / 4); i += 128) {
        int r  = i >> 5;
        int kq = (i & 31) << 2;
        int gr = row0 + r;
        float4 v = make_float4(0.f, 0.f, 0.f, 0.f);
        if (gr < n_nodes)
            v = *(const float4*)(x + (size_t)gr * D_IN + kq);
        Xs[kq + 0][r] = v.x;
        Xs[kq + 1][r] = v.y;
        Xs[kq + 2][r] = v.z;
        Xs[kq + 3][r] = v.w;
    }
    __syncthreads();

    int cg = (tid & 15) << 2;   // column base
    int rg = (tid >> 4) << 3;   // row base

    float acc[8][4];
    #pragma unroll
    for (int j = 0; j < 8; j++)
        #pragma unroll
        for (int c = 0; c < 4; c++) acc[j][c] = 0.f;

    #pragma unroll 4
    for (int k = 0; k < D_IN; k++) {
        float4 wv = __ldg((const float4*)(w + k * D_OUT + cg));
        float4 xa = *(const float4*)(&Xs[k][rg]);
        float4 xb = *(const float4*)(&Xs[k][rg + 4]);
        float xr[8] = {xa.x, xa.y, xa.z, xa.w, xb.x, xb.y, xb.z, xb.w};
        #pragma unroll
        for (int j = 0; j < 8; j++) {
            acc[j][0] += xr[j] * wv.x;
            acc[j][1] += xr[j] * wv.y;
            acc[j][2] += xr[j] * wv.z;
            acc[j][3] += xr[j] * wv.w;
        }
    }

    #pragma unroll
    for (int j = 0; j < 8; j++) {
        int gr = row0 + rg + j;
        if (gr < n_nodes)
            *(float4*)(g_h + (size_t)gr * D_OUT + cg) =
                make_float4(acc[j][0], acc[j][1], acc[j][2], acc[j][3]);
    }
}

// ---------------------------------------------------------------------------
// Warp-per-node aggregation.  Lane c owns columns [2c, 2c+1] (float2).
// 4-wide software pipeline: 4 independent src->h gather chains in flight.
// No atomics; bias fused into the final store.
// ---------------------------------------------------------------------------
__global__ void __launch_bounds__(256)
gather_kernel(const int*   __restrict__ src,
              const float* __restrict__ vals,
              const float* __restrict__ bias,
              float*       __restrict__ out,
              int n_nodes) {
    int gwarp = (blockIdx.x * 256 + threadIdx.x) >> 5;
    int lane  = threadIdx.x & 31;
    if (gwarp >= n_nodes) return;

    int e0 = g_row_ptr[gwarp];
    int e1 = g_row_ptr[gwarp + 1];

    const float2* hp = (const float2*)g_h;
    float ax0 = 0.f, ay0 = 0.f, ax1 = 0.f, ay1 = 0.f;

    int e = e0;
    for (; e + 4 <= e1; e += 4) {
        int   s0 = __ldg(src + e);
        int   s1 = __ldg(src + e + 1);
        int   s2 = __ldg(src + e + 2);
        int   s3 = __ldg(src + e + 3);
        float v0 = __ldg(vals + e);
        float v1 = __ldg(vals + e + 1);
        float v2 = __ldg(vals + e + 2);
        float v3 = __ldg(vals + e + 3);
        float2 h0 = hp[(size_t)s0 * 32 + lane];
        float2 h1 = hp[(size_t)s1 * 32 + lane];
        float2 h2 = hp[(size_t)s2 * 32 + lane];
        float2 h3 = hp[(size_t)s3 * 32 + lane];
        ax0 += v0 * h0.x + v1 * h1.x;
        ay0 += v0 * h0.y + v1 * h1.y;
        ax1 += v2 * h2.x + v3 * h3.x;
        ay1 += v2 * h2.y + v3 * h3.y;
    }
    for (; e < e1; e++) {
        int   s0 = __ldg(src + e);
        float v0 = __ldg(vals + e);
        float2 h0 = hp[(size_t)s0 * 32 + lane];
        ax0 += v0 * h0.x;
        ay0 += v0 * h0.y;
    }

    float2 b = __ldg((const float2*)bias + lane);
    ((float2*)out)[(size_t)gwarp * 32 + lane] =
        make_float2(ax0 + ax1 + b.x, ay0 + ay1 + b.y);
}

// ---------------------------------------------------------------------------
extern "C" void kernel_launch(void* const* d_in, const int* in_sizes, int n_in,
                              void* d_out, int out_size) {
    const float* x     = (const float*)d_in[0];
    const int*   esrc  = (const int*)  d_in[1];
    const int*   edst  = (const int*)  d_in[2];
    const float* evals = (const float*)d_in[3];
    const float* w     = (const float*)d_in[4];
    const float* bias  = (const float*)d_in[5];
    float*       out   = (float*)d_out;

    int n_nodes = in_sizes[0] / D_IN;
    int n_edges = in_sizes[1];

    rowptr_kernel<<<(n_edges + 255) / 256, 256>>>(edst, n_edges, n_nodes);

    gemm_kernel<<<(n_nodes + TM - 1) / TM, 128>>>(x, w, n_nodes);

    gather_kernel<<<(n_nodes * 32 + 255) / 256, 256>>>(esrc, evals, bias, out, n_nodes);
}